// round 5
// baseline (speedup 1.0000x reference)
#include <cuda_runtime.h>
#include <cstdint>

#define B_ 2
#define H_ 16
#define L_ 2048
#define D_ 64
#define BH_ (B_*H_)
#define NC_ 32            // chunks per bh (chunk = 64 rows)
#define EPS_ 1e-6f

// Scratch (device globals; allocation-free rule).
__device__ float g_qf[(size_t)BH_ * L_ * D_];            // relu(Q @ Wq)
__device__ float g_kf[(size_t)BH_ * L_ * D_];            // relu(K @ Wk)
__device__ float g_kv[(size_t)BH_ * NC_ * D_ * D_];      // per-chunk Kf^T V
__device__ float g_state[(size_t)BH_ * NC_ * D_ * D_];   // exclusive prefix of g_kv
__device__ float g_ks[(size_t)BH_ * NC_ * D_];           // per-chunk sum of kf
__device__ float g_zs[(size_t)BH_ * NC_ * D_];           // exclusive prefix of g_ks

// ===========================================================================
// Fused feature map + (key path) per-chunk KV/ksum.  128 rows per block.
// Grid (L/128, BH, 2); 256 threads; 8x4 micro-tiles.
// Dynamic smem 69632 B:
//   phase A: XT[64][136] (d, row) | Ws[64][68] (d, e)
//   phase B: Ks[128][68] (n, e)   | Vs[128][68] (n, e')   (aliased)
// ===========================================================================
#define FM_SMEM 69632

__global__ __launch_bounds__(256)
void fmap_kernel(const float* __restrict__ Q, const float* __restrict__ K,
                 const float* __restrict__ V,
                 const float* __restrict__ Wq, const float* __restrict__ Wk)
{
    extern __shared__ float sm[];
    float (*XT)[136] = (float(*)[136])sm;
    float (*Ws)[68]  = (float(*)[68])(sm + 64 * 136);

    const int tile = blockIdx.x, bh = blockIdx.y, sel = blockIdx.z;
    const int h = bh & (H_ - 1);
    const float* __restrict__ X = sel ? K : Q;
    const float* __restrict__ W = sel ? Wk : Wq;
    float* __restrict__ Outp = sel ? g_kf : g_qf;

    const int tid = threadIdx.x;
    const int row4 = tid >> 2, d0 = (tid & 3) << 4;
    const size_t rowbase = (size_t)bh * L_ + (size_t)tile * 128;

    // Load X (128 rows, transposed into XT) and W (64x64).
    #pragma unroll
    for (int rr = 0; rr < 128; rr += 64) {
        const float* src = X + (rowbase + rr + row4) * D_ + d0;
        #pragma unroll
        for (int i = 0; i < 4; i++) {
            float4 v = *(const float4*)(src + i * 4);
            XT[d0 + i*4 + 0][rr + row4] = v.x; XT[d0 + i*4 + 1][rr + row4] = v.y;
            XT[d0 + i*4 + 2][rr + row4] = v.z; XT[d0 + i*4 + 3][rr + row4] = v.w;
        }
    }
    {
        const float* wsrc = W + (size_t)h * D_ * D_ + (size_t)row4 * D_ + d0;
        #pragma unroll
        for (int i = 0; i < 4; i++)
            *(float4*)&Ws[row4][d0 + i*4] = *(const float4*)(wsrc + i * 4);
    }
    __syncthreads();

    const int ty = tid >> 4, tx = tid & 15;   // rows ty*8..+7, cols tx*4..+3
    float acc[8][4] = {};
    #pragma unroll 4
    for (int d = 0; d < 64; d++) {
        float4 a0 = *(const float4*)&XT[d][ty * 8];
        float4 a1 = *(const float4*)&XT[d][ty * 8 + 4];
        float4 b  = *(const float4*)&Ws[d][tx * 4];
        float av[8] = {a0.x, a0.y, a0.z, a0.w, a1.x, a1.y, a1.z, a1.w};
        float bv[4] = {b.x, b.y, b.z, b.w};
        #pragma unroll
        for (int r = 0; r < 8; r++)
            #pragma unroll
            for (int c = 0; c < 4; c++)
                acc[r][c] = fmaf(av[r], bv[c], acc[r][c]);
    }
    #pragma unroll
    for (int r = 0; r < 8; r++)
        #pragma unroll
        for (int c = 0; c < 4; c++)
            acc[r][c] = fmaxf(acc[r][c], 0.f);

    {
        float* dst = Outp + (rowbase + ty * 8) * D_ + tx * 4;
        #pragma unroll
        for (int r = 0; r < 8; r++)
            *(float4*)(dst + (size_t)r * D_) =
                make_float4(acc[r][0], acc[r][1], acc[r][2], acc[r][3]);
    }

    if (!sel) return;

    // ---- key path: KV_c = Kf_c^T @ V_c for the 2 chunks in this block ----
    __syncthreads();   // phase-A smem reads done
    float (*Ks)[68]  = (float(*)[68])sm;            // kf rows [n][e]
    float (*Vs2)[68] = (float(*)[68])(sm + 128 * 68);

    #pragma unroll
    for (int r = 0; r < 8; r++)
        *(float4*)&Ks[ty * 8 + r][tx * 4] =
            make_float4(acc[r][0], acc[r][1], acc[r][2], acc[r][3]);
    #pragma unroll
    for (int rr = 0; rr < 128; rr += 64) {
        const float* vs = V + (rowbase + rr + row4) * D_ + d0;
        #pragma unroll
        for (int i = 0; i < 4; i++)
            *(float4*)&Vs2[rr + row4][d0 + i*4] = *(const float4*)(vs + i * 4);
    }
    __syncthreads();

    // warps 0-3 -> chunk 0, warps 4-7 -> chunk 1 (warp-uniform).
    const int chunk = ty >> 3, tyc = ty & 7;
    const int nbase = chunk * 64;
    float kv[8][4] = {};
    #pragma unroll 4
    for (int n = 0; n < 64; n++) {
        float4 a0 = *(const float4*)&Ks[nbase + n][tyc * 8];
        float4 a1 = *(const float4*)&Ks[nbase + n][tyc * 8 + 4];
        float4 b  = *(const float4*)&Vs2[nbase + n][tx * 4];
        float av[8] = {a0.x, a0.y, a0.z, a0.w, a1.x, a1.y, a1.z, a1.w};
        float bv[4] = {b.x, b.y, b.z, b.w};
        #pragma unroll
        for (int r = 0; r < 8; r++)
            #pragma unroll
            for (int c = 0; c < 4; c++)
                kv[r][c] = fmaf(av[r], bv[c], kv[r][c]);
    }

    {
        float* kvdst = g_kv + ((size_t)(bh * NC_ + tile * 2 + chunk) * D_
                               + tyc * 8) * D_ + tx * 4;
        #pragma unroll
        for (int r = 0; r < 8; r++)
            *(float4*)(kvdst + (size_t)r * D_) =
                make_float4(kv[r][0], kv[r][1], kv[r][2], kv[r][3]);
    }

    if (tid < 128) {   // ksum per chunk
        const int c2 = tid >> 6, d = tid & 63;
        float s = 0.f;
        #pragma unroll 8
        for (int n = 0; n < 64; n++) s += Ks[c2 * 64 + n][d];
        g_ks[(size_t)(bh * NC_ + tile * 2 + c2) * D_ + d] = s;
    }
}

// ===========================================================================
// Exclusive prefix scan over chunks (per bh, per element).
// ===========================================================================
__global__ __launch_bounds__(256)
void scan_kernel()
{
    const int g = blockIdx.x, bh = blockIdx.y, tid = threadIdx.x;
    if (g < 16) {
        const int e = g * 256 + tid;
        float acc = 0.f;
        #pragma unroll
        for (int c = 0; c < NC_; c++) {
            const size_t idx = (size_t)(bh * NC_ + c) * (D_ * D_) + e;
            g_state[idx] = acc;
            acc += g_kv[idx];
        }
    } else if (tid < 64) {
        float acc = 0.f;
        #pragma unroll
        for (int c = 0; c < NC_; c++) {
            const size_t idx = (size_t)(bh * NC_ + c) * D_ + tid;
            g_zs[idx] = acc;
            acc += g_ks[idx];
        }
    }
}

// ===========================================================================
// Per-chunk output (128 threads, 8x4 micro-tiles):
//   S = tril(Qf_c @ Kf_c^T); O = S @ V_c + Qf_c @ state_c
//   denom = rowsum(S) + qf . z_c + EPS
// GEMM2 n-loop is warp-bounded by causality (warp w: n < 16w+16).
// Grid (NC, BH); 70400 B dynamic smem; kT reused as S^T.
// ===========================================================================
#define OUT_SMEM ((4 * 64 * 68 + 192) * 4)

__global__ __launch_bounds__(128, 3)
void out_kernel(const float* __restrict__ V, float* __restrict__ Out)
{
    extern __shared__ float sm[];
    float (*qT)[68]  = (float(*)[68])(sm);                 // qT[d][m]
    float (*kT)[68]  = (float(*)[68])(sm + 1 * 64 * 68);   // kT[d][n] -> St[n][m]
    float (*Vs)[68]  = (float(*)[68])(sm + 2 * 64 * 68);   // Vs[n][e]
    float (*Sts)[68] = (float(*)[68])(sm + 3 * 64 * 68);   // state[d][e]
    float* rowsum    = sm + 4 * 64 * 68;                   // [64]
    float* qz        = rowsum + 64;                        // [64]
    float* zs        = qz + 64;                            // [64]

    const int c = blockIdx.x, bh = blockIdx.y;
    const int tid = threadIdx.x;
    const int ty = tid >> 4, tx = tid & 15;   // ty 0..7: rows ty*8..+7
    const size_t rowbase = (size_t)bh * L_ + (size_t)c * 64;
    const size_t chunk = (size_t)(bh * NC_ + c);

    {
        const int row = tid >> 1, d0 = (tid & 1) << 5;    // 64 rows, 2 half-rows
        const float* qs = g_qf + (rowbase + row) * D_ + d0;
        const float* ks = g_kf + (rowbase + row) * D_ + d0;
        const float* vs = V    + (rowbase + row) * D_ + d0;
        const float* ss = g_state + (chunk * D_ + row) * D_ + d0;
        #pragma unroll
        for (int i = 0; i < 8; i++) {
            float4 q4 = *(const float4*)(qs + i * 4);
            qT[d0 + i*4 + 0][row] = q4.x; qT[d0 + i*4 + 1][row] = q4.y;
            qT[d0 + i*4 + 2][row] = q4.z; qT[d0 + i*4 + 3][row] = q4.w;
            float4 k4 = *(const float4*)(ks + i * 4);
            kT[d0 + i*4 + 0][row] = k4.x; kT[d0 + i*4 + 1][row] = k4.y;
            kT[d0 + i*4 + 2][row] = k4.z; kT[d0 + i*4 + 3][row] = k4.w;
            *(float4*)&Vs[row][d0 + i*4]  = *(const float4*)(vs + i * 4);
            *(float4*)&Sts[row][d0 + i*4] = *(const float4*)(ss + i * 4);
        }
        if (tid < 64) zs[tid] = g_zs[chunk * D_ + tid];
    }
    __syncthreads();

    // ---- GEMM1: S = Qf Kf^T (full d), then causal mask ----
    float s[8][4] = {};
    #pragma unroll 4
    for (int d = 0; d < 64; d++) {
        float4 a0 = *(const float4*)&qT[d][ty * 8];
        float4 a1 = *(const float4*)&qT[d][ty * 8 + 4];
        float4 b  = *(const float4*)&kT[d][tx * 4];
        float av[8] = {a0.x, a0.y, a0.z, a0.w, a1.x, a1.y, a1.z, a1.w};
        float bv[4] = {b.x, b.y, b.z, b.w};
        #pragma unroll
        for (int r = 0; r < 8; r++)
            #pragma unroll
            for (int cc = 0; cc < 4; cc++)
                s[r][cc] = fmaf(av[r], bv[cc], s[r][cc]);
    }
    #pragma unroll
    for (int r = 0; r < 8; r++)
        #pragma unroll
        for (int cc = 0; cc < 4; cc++)
            if (tx * 4 + cc > ty * 8 + r) s[r][cc] = 0.f;

    // rowsum via shfl across the 16 tx lanes (xor<=8 stays in half-warp).
    #pragma unroll
    for (int r = 0; r < 8; r++) {
        float p = (s[r][0] + s[r][1]) + (s[r][2] + s[r][3]);
        p += __shfl_xor_sync(0xffffffffu, p, 1);
        p += __shfl_xor_sync(0xffffffffu, p, 2);
        p += __shfl_xor_sync(0xffffffffu, p, 4);
        p += __shfl_xor_sync(0xffffffffu, p, 8);
        if (tx == 0) rowsum[ty * 8 + r] = p;
    }
    if (tid < 64) {   // qz[m] = qf[m] . z_prev
        float acc = 0.f;
        #pragma unroll 8
        for (int d = 0; d < 64; d++) acc = fmaf(qT[d][tid], zs[d], acc);
        qz[tid] = acc;
    }

    __syncthreads();   // kT reads done; overwrite with S^T
    float (*St)[68] = kT;   // St[n][m]
    #pragma unroll
    for (int cc = 0; cc < 4; cc++) {
        *(float4*)&St[tx * 4 + cc][ty * 8] =
            make_float4(s[0][cc], s[1][cc], s[2][cc], s[3][cc]);
        *(float4*)&St[tx * 4 + cc][ty * 8 + 4] =
            make_float4(s[4][cc], s[5][cc], s[6][cc], s[7][cc]);
    }
    __syncthreads();

    // ---- GEMM2: O = S @ V  (n bounded by causality, warp-uniform) ----
    float o[8][4] = {};
    const int nmax = ((ty >> 1) << 4) + 16;   // warp w: rows <= 16w+15
    #pragma unroll 4
    for (int n = 0; n < nmax; n++) {
        float4 a0 = *(const float4*)&St[n][ty * 8];
        float4 a1 = *(const float4*)&St[n][ty * 8 + 4];
        float4 b  = *(const float4*)&Vs[n][tx * 4];
        float av[8] = {a0.x, a0.y, a0.z, a0.w, a1.x, a1.y, a1.z, a1.w};
        float bv[4] = {b.x, b.y, b.z, b.w};
        #pragma unroll
        for (int r = 0; r < 8; r++)
            #pragma unroll
            for (int cc = 0; cc < 4; cc++)
                o[r][cc] = fmaf(av[r], bv[cc], o[r][cc]);
    }
    // ---- GEMM3: O += Qf @ state ----
    #pragma unroll 4
    for (int d = 0; d < 64; d++) {
        float4 a0 = *(const float4*)&qT[d][ty * 8];
        float4 a1 = *(const float4*)&qT[d][ty * 8 + 4];
        float4 b  = *(const float4*)&Sts[d][tx * 4];
        float av[8] = {a0.x, a0.y, a0.z, a0.w, a1.x, a1.y, a1.z, a1.w};
        float bv[4] = {b.x, b.y, b.z, b.w};
        #pragma unroll
        for (int r = 0; r < 8; r++)
            #pragma unroll
            for (int cc = 0; cc < 4; cc++)
                o[r][cc] = fmaf(av[r], bv[cc], o[r][cc]);
    }

    float* dst = Out + (rowbase + ty * 8) * D_ + tx * 4;
    #pragma unroll
    for (int r = 0; r < 8; r++) {
        const float inv = 1.0f / (rowsum[ty * 8 + r] + qz[ty * 8 + r] + EPS_);
        *(float4*)(dst + (size_t)r * D_) =
            make_float4(o[r][0] * inv, o[r][1] * inv, o[r][2] * inv, o[r][3] * inv);
    }
}

// ===========================================================================
extern "C" void kernel_launch(void* const* d_in, const int* in_sizes, int n_in,
                              void* d_out, int out_size)
{
    (void)in_sizes; (void)n_in; (void)out_size;
    const float* Q  = (const float*)d_in[0];
    const float* K  = (const float*)d_in[1];
    const float* V  = (const float*)d_in[2];
    const float* Wq = (const float*)d_in[3];
    const float* Wk = (const float*)d_in[4];
    float* Out = (float*)d_out;

    cudaFuncSetAttribute(fmap_kernel,
                         cudaFuncAttributeMaxDynamicSharedMemorySize, FM_SMEM);
    cudaFuncSetAttribute(out_kernel,
                         cudaFuncAttributeMaxDynamicSharedMemorySize, OUT_SMEM);

    fmap_kernel<<<dim3(L_ / 128, BH_, 2), 256, FM_SMEM>>>(Q, K, V, Wq, Wk);
    scan_kernel<<<dim3(17, BH_), 256>>>();
    out_kernel<<<dim3(NC_, BH_), 128, OUT_SMEM>>>(V, Out);
}

// round 6
// speedup vs baseline: 1.2489x; 1.2489x over previous
#include <cuda_runtime.h>
#include <cstdint>

#define B_ 2
#define H_ 16
#define L_ 2048
#define D_ 64
#define BH_ (B_*H_)
#define NC_ 32            // chunks per bh (chunk = 64 rows)
#define EPS_ 1e-6f

// Scratch (device globals; allocation-free rule).
__device__ float g_qf[(size_t)BH_ * L_ * D_];            // relu(Q @ Wq)
__device__ float g_kf[(size_t)BH_ * L_ * D_];            // relu(K @ Wk)
__device__ float g_kv[(size_t)BH_ * NC_ * D_ * D_];      // per-chunk Kf^T V
__device__ float g_state[(size_t)BH_ * NC_ * D_ * D_];   // exclusive prefix of g_kv
__device__ float g_ks[(size_t)BH_ * NC_ * D_];           // per-chunk sum of kf
__device__ float g_zs[(size_t)BH_ * NC_ * D_];           // exclusive prefix of g_ks

// ===========================================================================
// Fused feature map + (key path) per-chunk KV/ksum.  128 rows per block.
// Grid (L/128, BH, 2); 256 threads; 8x4 micro-tiles.  (round-5, measured 51.7us)
// ===========================================================================
#define FM_SMEM 69632

__global__ __launch_bounds__(256)
void fmap_kernel(const float* __restrict__ Q, const float* __restrict__ K,
                 const float* __restrict__ V,
                 const float* __restrict__ Wq, const float* __restrict__ Wk)
{
    extern __shared__ float sm[];
    float (*XT)[136] = (float(*)[136])sm;
    float (*Ws)[68]  = (float(*)[68])(sm + 64 * 136);

    const int tile = blockIdx.x, bh = blockIdx.y, sel = blockIdx.z;
    const int h = bh & (H_ - 1);
    const float* __restrict__ X = sel ? K : Q;
    const float* __restrict__ W = sel ? Wk : Wq;
    float* __restrict__ Outp = sel ? g_kf : g_qf;

    const int tid = threadIdx.x;
    const int row4 = tid >> 2, d0 = (tid & 3) << 4;
    const size_t rowbase = (size_t)bh * L_ + (size_t)tile * 128;

    #pragma unroll
    for (int rr = 0; rr < 128; rr += 64) {
        const float* src = X + (rowbase + rr + row4) * D_ + d0;
        #pragma unroll
        for (int i = 0; i < 4; i++) {
            float4 v = *(const float4*)(src + i * 4);
            XT[d0 + i*4 + 0][rr + row4] = v.x; XT[d0 + i*4 + 1][rr + row4] = v.y;
            XT[d0 + i*4 + 2][rr + row4] = v.z; XT[d0 + i*4 + 3][rr + row4] = v.w;
        }
    }
    {
        const float* wsrc = W + (size_t)h * D_ * D_ + (size_t)row4 * D_ + d0;
        #pragma unroll
        for (int i = 0; i < 4; i++)
            *(float4*)&Ws[row4][d0 + i*4] = *(const float4*)(wsrc + i * 4);
    }
    __syncthreads();

    const int ty = tid >> 4, tx = tid & 15;   // rows ty*8..+7, cols tx*4..+3
    float acc[8][4] = {};
    #pragma unroll 4
    for (int d = 0; d < 64; d++) {
        float4 a0 = *(const float4*)&XT[d][ty * 8];
        float4 a1 = *(const float4*)&XT[d][ty * 8 + 4];
        float4 b  = *(const float4*)&Ws[d][tx * 4];
        float av[8] = {a0.x, a0.y, a0.z, a0.w, a1.x, a1.y, a1.z, a1.w};
        float bv[4] = {b.x, b.y, b.z, b.w};
        #pragma unroll
        for (int r = 0; r < 8; r++)
            #pragma unroll
            for (int c = 0; c < 4; c++)
                acc[r][c] = fmaf(av[r], bv[c], acc[r][c]);
    }
    #pragma unroll
    for (int r = 0; r < 8; r++)
        #pragma unroll
        for (int c = 0; c < 4; c++)
            acc[r][c] = fmaxf(acc[r][c], 0.f);

    {
        float* dst = Outp + (rowbase + ty * 8) * D_ + tx * 4;
        #pragma unroll
        for (int r = 0; r < 8; r++)
            *(float4*)(dst + (size_t)r * D_) =
                make_float4(acc[r][0], acc[r][1], acc[r][2], acc[r][3]);
    }

    if (!sel) return;

    // ---- key path: KV_c = Kf_c^T @ V_c for the 2 chunks in this block ----
    __syncthreads();
    float (*Ks)[68]  = (float(*)[68])sm;
    float (*Vs2)[68] = (float(*)[68])(sm + 128 * 68);

    #pragma unroll
    for (int r = 0; r < 8; r++)
        *(float4*)&Ks[ty * 8 + r][tx * 4] =
            make_float4(acc[r][0], acc[r][1], acc[r][2], acc[r][3]);
    #pragma unroll
    for (int rr = 0; rr < 128; rr += 64) {
        const float* vs = V + (rowbase + rr + row4) * D_ + d0;
        #pragma unroll
        for (int i = 0; i < 4; i++)
            *(float4*)&Vs2[rr + row4][d0 + i*4] = *(const float4*)(vs + i * 4);
    }
    __syncthreads();

    const int chunk = ty >> 3, tyc = ty & 7;
    const int nbase = chunk * 64;
    float kv[8][4] = {};
    #pragma unroll 4
    for (int n = 0; n < 64; n++) {
        float4 a0 = *(const float4*)&Ks[nbase + n][tyc * 8];
        float4 a1 = *(const float4*)&Ks[nbase + n][tyc * 8 + 4];
        float4 b  = *(const float4*)&Vs2[nbase + n][tx * 4];
        float av[8] = {a0.x, a0.y, a0.z, a0.w, a1.x, a1.y, a1.z, a1.w};
        float bv[4] = {b.x, b.y, b.z, b.w};
        #pragma unroll
        for (int r = 0; r < 8; r++)
            #pragma unroll
            for (int c = 0; c < 4; c++)
                kv[r][c] = fmaf(av[r], bv[c], kv[r][c]);
    }
    {
        float* kvdst = g_kv + ((size_t)(bh * NC_ + tile * 2 + chunk) * D_
                               + tyc * 8) * D_ + tx * 4;
        #pragma unroll
        for (int r = 0; r < 8; r++)
            *(float4*)(kvdst + (size_t)r * D_) =
                make_float4(kv[r][0], kv[r][1], kv[r][2], kv[r][3]);
    }
    if (tid < 128) {
        const int c2 = tid >> 6, d = tid & 63;
        float s = 0.f;
        #pragma unroll 8
        for (int n = 0; n < 64; n++) s += Ks[c2 * 64 + n][d];
        g_ks[(size_t)(bh * NC_ + tile * 2 + c2) * D_ + d] = s;
    }
}

// ===========================================================================
// Exclusive prefix scan over chunks (per bh, per element).
// ===========================================================================
__global__ __launch_bounds__(256)
void scan_kernel()
{
    const int g = blockIdx.x, bh = blockIdx.y, tid = threadIdx.x;
    if (g < 16) {
        const int e = g * 256 + tid;
        float acc = 0.f;
        #pragma unroll
        for (int c = 0; c < NC_; c++) {
            const size_t idx = (size_t)(bh * NC_ + c) * (D_ * D_) + e;
            g_state[idx] = acc;
            acc += g_kv[idx];
        }
    } else if (tid < 64) {
        float acc = 0.f;
        #pragma unroll
        for (int c = 0; c < NC_; c++) {
            const size_t idx = (size_t)(bh * NC_ + c) * D_ + tid;
            g_zs[idx] = acc;
            acc += g_ks[idx];
        }
    }
}

// ===========================================================================
// Per-chunk output (round-4 shape: 256 threads, 4x4 micro-tiles, 3 CTAs/SM)
// + causal GEMM2 bound: warp w covers rows 8w..8w+7 -> n < 8w+8.
// Grid (NC, BH); 70400 B dynamic smem; kT reused as S^T.
// ===========================================================================
#define OUT_SMEM ((4 * 64 * 68 + 192) * 4)

__global__ __launch_bounds__(256, 3)
void out_kernel(const float* __restrict__ V, float* __restrict__ Out)
{
    extern __shared__ float sm[];
    float (*qT)[68]  = (float(*)[68])(sm);                 // qT[d][m]
    float (*kT)[68]  = (float(*)[68])(sm + 1 * 64 * 68);   // kT[d][n] -> St[n][m]
    float (*Vs)[68]  = (float(*)[68])(sm + 2 * 64 * 68);   // Vs[n][e]
    float (*Sts)[68] = (float(*)[68])(sm + 3 * 64 * 68);   // state[d][e]
    float* rowsum    = sm + 4 * 64 * 68;                   // [64]
    float* qz        = rowsum + 64;                        // [64]
    float* zs        = qz + 64;                            // [64]

    const int c = blockIdx.x, bh = blockIdx.y;
    const int tid = threadIdx.x;
    const int ty = tid >> 4, tx = tid & 15;
    const size_t rowbase = (size_t)bh * L_ + (size_t)c * 64;
    const size_t chunk = (size_t)(bh * NC_ + c);

    {
        const int row = tid >> 2, d0 = (tid & 3) << 4;
        const float* qs = g_qf + (rowbase + row) * D_ + d0;
        const float* ks = g_kf + (rowbase + row) * D_ + d0;
        const float* vs = V    + (rowbase + row) * D_ + d0;
        const float* ss = g_state + (chunk * D_ + row) * D_ + d0;
        #pragma unroll
        for (int i = 0; i < 4; i++) {
            float4 q4 = *(const float4*)(qs + i * 4);
            qT[d0 + i*4 + 0][row] = q4.x; qT[d0 + i*4 + 1][row] = q4.y;
            qT[d0 + i*4 + 2][row] = q4.z; qT[d0 + i*4 + 3][row] = q4.w;
            float4 k4 = *(const float4*)(ks + i * 4);
            kT[d0 + i*4 + 0][row] = k4.x; kT[d0 + i*4 + 1][row] = k4.y;
            kT[d0 + i*4 + 2][row] = k4.z; kT[d0 + i*4 + 3][row] = k4.w;
            *(float4*)&Vs[row][d0 + i*4]  = *(const float4*)(vs + i * 4);
            *(float4*)&Sts[row][d0 + i*4] = *(const float4*)(ss + i * 4);
        }
        if (tid < 64) zs[tid] = g_zs[chunk * D_ + tid];
    }
    __syncthreads();

    // ---- GEMM1: S = tril(Qf Kf^T); rowsum via shfl; qz = qf . z_prev ----
    float s[4][4] = {};
    #pragma unroll 8
    for (int d = 0; d < 64; d++) {
        float4 a = *(const float4*)&qT[d][ty * 4];
        float4 b = *(const float4*)&kT[d][tx * 4];
        float av[4] = {a.x, a.y, a.z, a.w};
        float bv[4] = {b.x, b.y, b.z, b.w};
        #pragma unroll
        for (int r = 0; r < 4; r++)
            #pragma unroll
            for (int cc = 0; cc < 4; cc++)
                s[r][cc] = fmaf(av[r], bv[cc], s[r][cc]);
    }
    #pragma unroll
    for (int r = 0; r < 4; r++)
        #pragma unroll
        for (int cc = 0; cc < 4; cc++)
            if (tx * 4 + cc > ty * 4 + r) s[r][cc] = 0.f;   // causal within chunk

    #pragma unroll
    for (int r = 0; r < 4; r++) {
        float p = (s[r][0] + s[r][1]) + (s[r][2] + s[r][3]);
        p += __shfl_xor_sync(0xffffffffu, p, 1);
        p += __shfl_xor_sync(0xffffffffu, p, 2);
        p += __shfl_xor_sync(0xffffffffu, p, 4);
        p += __shfl_xor_sync(0xffffffffu, p, 8);
        if (tx == 0) rowsum[ty * 4 + r] = p;
    }
    if (tid < 64) {
        float acc = 0.f;
        #pragma unroll 8
        for (int d = 0; d < 64; d++) acc = fmaf(qT[d][tid], zs[d], acc);
        qz[tid] = acc;
    }

    __syncthreads();   // all kT reads done; safe to overwrite with S^T
    float (*St)[68] = kT;   // St[n][m]
    #pragma unroll
    for (int cc = 0; cc < 4; cc++)
        *(float4*)&St[tx * 4 + cc][ty * 4] =
            make_float4(s[0][cc], s[1][cc], s[2][cc], s[3][cc]);
    __syncthreads();

    // ---- GEMM2: O = S @ V (causal bound: warp w rows <= 8w+7 -> n < 8w+8) ----
    float o[4][4] = {};
    const int nmax = ((tid >> 5) << 3) + 8;
    #pragma unroll 8
    for (int n = 0; n < nmax; n++) {
        float4 a = *(const float4*)&St[n][ty * 4];   // S[m block][n]
        float4 b = *(const float4*)&Vs[n][tx * 4];
        float av[4] = {a.x, a.y, a.z, a.w};
        float bv[4] = {b.x, b.y, b.z, b.w};
        #pragma unroll
        for (int r = 0; r < 4; r++)
            #pragma unroll
            for (int cc = 0; cc < 4; cc++)
                o[r][cc] = fmaf(av[r], bv[cc], o[r][cc]);
    }
    // ---- GEMM3: O += Qf @ state ----
    #pragma unroll 8
    for (int d = 0; d < 64; d++) {
        float4 a = *(const float4*)&qT[d][ty * 4];
        float4 b = *(const float4*)&Sts[d][tx * 4];
        float av[4] = {a.x, a.y, a.z, a.w};
        float bv[4] = {b.x, b.y, b.z, b.w};
        #pragma unroll
        for (int r = 0; r < 4; r++)
            #pragma unroll
            for (int cc = 0; cc < 4; cc++)
                o[r][cc] = fmaf(av[r], bv[cc], o[r][cc]);
    }

    float* dst = Out + (rowbase + ty * 4) * D_ + tx * 4;
    #pragma unroll
    for (int r = 0; r < 4; r++) {
        const float inv = 1.0f / (rowsum[ty * 4 + r] + qz[ty * 4 + r] + EPS_);
        *(float4*)(dst + (size_t)r * D_) =
            make_float4(o[r][0] * inv, o[r][1] * inv, o[r][2] * inv, o[r][3] * inv);
    }
}

// ===========================================================================
extern "C" void kernel_launch(void* const* d_in, const int* in_sizes, int n_in,
                              void* d_out, int out_size)
{
    (void)in_sizes; (void)n_in; (void)out_size;
    const float* Q  = (const float*)d_in[0];
    const float* K  = (const float*)d_in[1];
    const float* V  = (const float*)d_in[2];
    const float* Wq = (const float*)d_in[3];
    const float* Wk = (const float*)d_in[4];
    float* Out = (float*)d_out;

    cudaFuncSetAttribute(fmap_kernel,
                         cudaFuncAttributeMaxDynamicSharedMemorySize, FM_SMEM);
    cudaFuncSetAttribute(out_kernel,
                         cudaFuncAttributeMaxDynamicSharedMemorySize, OUT_SMEM);

    fmap_kernel<<<dim3(L_ / 128, BH_, 2), 256, FM_SMEM>>>(Q, K, V, Wq, Wk);
    scan_kernel<<<dim3(17, BH_), 256>>>();
    out_kernel<<<dim3(NC_, BH_), 256, OUT_SMEM>>>(V, Out);
}